// round 15
// baseline (speedup 1.0000x reference)
#include <cuda_runtime.h>
#include <cuda_bf16.h>

// Problem shapes (fixed by the dataset)
#define BB   128            // batch = grid
#define NN   256            // boxes per batch = block
#define WW   256
#define HW   (256 * 256)    // 65536
#define NWARPS_TOTAL (BB * NN / 32)   // 1024

// Per-warp 32-bit pack (REDUX.SUM-safe):
//   bits [0,24)  = sum(loss * 2^16)  (max 32 * 2^16 = 2^21)
//   bits [24,32) = count             (max 32)
// Global 64-bit pack, one atomicAdd PER WARP (no block stage, no smem):
//   bits [0,36)  = sum(loss * 2^16)  (max 32768 * 2^16 = 2^31)
//   bits [36,52) = count             (max 32768)
//   bits [52,64) = warp arrivals     (1024 < 4096)
// Atomic RMWs on one address are totally ordered, so the warp whose post-add
// arrival field equals NWARPS_TOTAL holds the complete sum — no fence, no
// second counter, no reload. Integer adds are associative => deterministic
// result independent of arrival order (bit-exact across graph replays).
__device__ unsigned long long g_acc = 0ULL;

#define Q_SCALE   65536.0f               // 2^16
#define WCNT_ONE  (1u << 24)
#define GCNT_SH   36
#define WARP_ONE  (1ULL << 52)
#define GSUM_MASK ((1ULL << 36) - 1)

__global__ __launch_bounds__(NN) void iou_loss_fused(
    const float* __restrict__ out,      // [B, 2, H, W]
    const float* __restrict__ target,   // [B, N, 2]
    const int*   __restrict__ ind,      // [B, N]
    const int*   __restrict__ mask,     // [B, N] (bool promoted to int32)
    float*       __restrict__ d_out)
{
    const int b   = blockIdx.x;
    const int n   = threadIdx.x;
    const int idx = b * NN + n;

    // front-batched independent loads (mask/ind/target issue in parallel)
    const int    mk = mask[idx];
    const int    id = ind[idx];
    const float2 tg = reinterpret_cast<const float2*>(target)[idx];

    unsigned int val = 0u;

    if (mk != 0) {
        // conditional gathers: halves hot-replay L2 traffic (R11 isolation:
        // measured faster than unconditional in the timed steady state)
        const float* base = out + (unsigned)b * (2 * HW);
        const float dx = __ldg(base + id);        // channel 0
        const float dy = __ldg(base + HW + id);   // channel 1

        const float tx = tg.x, ty = tg.y;
        const float x  = (float)(id & (WW - 1));
        const float y  = (float)(id >> 8);

        // trunc toward zero, matching torch .int() / jnp.trunc
        const float gx = truncf(x - tx * 0.5f);
        const float gy = truncf(y - ty * 0.5f);
        const float px = truncf(x - dx * 0.5f);
        const float py = truncf(y - dy * 0.5f);

        const float g_x1 = gx - tx * 0.5f, g_x2 = gx + tx * 0.5f;
        const float g_y1 = gy - ty * 0.5f, g_y2 = gy + ty * 0.5f;
        const float d_x1 = px - dx * 0.5f, d_x2 = px + dx * 0.5f;
        const float d_y1 = py - dy * 0.5f, d_y2 = py + dy * 0.5f;

        const float iw = fmaxf(fminf(g_x2, d_x2) - fmaxf(g_x1, d_x1), 0.0f);
        const float ih = fmaxf(fminf(g_y2, d_y2) - fmaxf(g_y1, d_y1), 0.0f);
        const float inter = iw * ih;

        const float w1 = g_x2 - g_x1, h1 = g_y2 - g_y1;
        const float w2 = d_x2 - d_x1, h2 = d_y2 - d_y1;
        const float uni = w1 * h1 + 1e-16f + w2 * h2 - inter;

        // loss in [0,1]; clamp against ulp overshoot before unsigned cast
        const float loss = fmaxf(1.0f - inter / uni, 0.0f);
        val = (unsigned int)(loss * Q_SCALE) + WCNT_ONE;
    }

    // ── one REDUX, then straight to the single global atomic ──
    const unsigned int wsum = __reduce_add_sync(0xFFFFFFFFu, val);

    if ((n & 31) == 0) {
        const unsigned long long v =
              (unsigned long long)(wsum & 0xFFFFFF)
            + ((unsigned long long)(wsum >> 24) << GCNT_SH)
            + WARP_ONE;

        const unsigned long long total = atomicAdd(&g_acc, v) + v;

        if ((unsigned)(total >> 52) == NWARPS_TOTAL) {
            // atomic total order: this warp holds the complete sum — finalize
            const float sumf = (float)(total & GSUM_MASK) * (1.0f / Q_SCALE);
            const float cnt  = (float)(unsigned)((total >> GCNT_SH) & 0xFFFF);
            d_out[0] = sumf / (4.0f * cnt + 0.0001f);
            g_acc = 0ULL;                 // reset for next graph replay
        }
    }
}

extern "C" void kernel_launch(void* const* d_in, const int* in_sizes, int n_in,
                              void* d_out, int out_size)
{
    const float* out_map = (const float*)d_in[0];  // [128,2,256,256] f32
    const float* target  = (const float*)d_in[1];  // [128,256,2]     f32
    const int*   ind     = (const int*)  d_in[2];  // [128,256]       i32
    const int*   mask    = (const int*)  d_in[3];  // [128,256]       i32 (bool)
    float*       outp    = (float*)d_out;

    iou_loss_fused<<<BB, NN>>>(out_map, target, ind, mask, outp);
}

// round 16
// speedup vs baseline: 1.0769x; 1.0769x over previous
#include <cuda_runtime.h>
#include <cuda_bf16.h>

// Problem shapes (fixed by the dataset)
#define BB   128            // batch = grid
#define NN   256            // boxes per batch = block
#define WW   256
#define HW   (256 * 256)    // 65536
#define NWARPS_TOTAL (BB * NN / 32)   // 1024

// Per-warp 32-bit pack (REDUX.SUM-safe):
//   bits [0,24)  = sum(loss * 2^16)  (max 32 * 2^16 = 2^21)
//   bits [24,32) = count             (max 32)
// Global 64-bit pack, one atomicAdd PER WARP (no block stage, no smem):
//   bits [0,36)  = sum(loss * 2^16)  (max 32768 * 2^16 = 2^31)
//   bits [36,52) = count             (max 32768)
//   bits [52,64) = warp arrivals     (1024 < 4096)
// Atomic RMWs on one address are totally ordered, so the warp whose post-add
// arrival field equals NWARPS_TOTAL holds the complete sum — no fence, no
// second counter, no reload. Integer adds are associative => deterministic
// result independent of arrival order (bit-exact across graph replays).
__device__ unsigned long long g_acc = 0ULL;

#define Q_SCALE   65536.0f               // 2^16
#define WCNT_ONE  (1u << 24)
#define GCNT_SH   36
#define WARP_ONE  (1ULL << 52)
#define GSUM_MASK ((1ULL << 36) - 1)

__global__ __launch_bounds__(NN) void iou_loss_fused(
    const float* __restrict__ out,      // [B, 2, H, W]
    const float* __restrict__ target,   // [B, N, 2]
    const int*   __restrict__ ind,      // [B, N]
    const int*   __restrict__ mask,     // [B, N] (bool promoted to int32)
    float*       __restrict__ d_out)
{
    const int b   = blockIdx.x;
    const int n   = threadIdx.x;
    const int idx = b * NN + n;

    // front-batched independent loads (mask/ind/target issue in parallel)
    const int    mk = mask[idx];
    const int    id = ind[idx];
    const float2 tg = reinterpret_cast<const float2*>(target)[idx];

    unsigned int val = 0u;

    if (mk != 0) {
        // conditional gathers: halves hot-replay L2 traffic (R11 isolation:
        // measured faster than unconditional in the timed steady state)
        const float* base = out + (unsigned)b * (2 * HW);
        const float dx = __ldg(base + id);        // channel 0
        const float dy = __ldg(base + HW + id);   // channel 1

        const float tx = tg.x, ty = tg.y;
        const float x  = (float)(id & (WW - 1));
        const float y  = (float)(id >> 8);

        // trunc toward zero, matching torch .int() / jnp.trunc
        const float gx = truncf(x - tx * 0.5f);
        const float gy = truncf(y - ty * 0.5f);
        const float px = truncf(x - dx * 0.5f);
        const float py = truncf(y - dy * 0.5f);

        const float g_x1 = gx - tx * 0.5f, g_x2 = gx + tx * 0.5f;
        const float g_y1 = gy - ty * 0.5f, g_y2 = gy + ty * 0.5f;
        const float d_x1 = px - dx * 0.5f, d_x2 = px + dx * 0.5f;
        const float d_y1 = py - dy * 0.5f, d_y2 = py + dy * 0.5f;

        const float iw = fmaxf(fminf(g_x2, d_x2) - fmaxf(g_x1, d_x1), 0.0f);
        const float ih = fmaxf(fminf(g_y2, d_y2) - fmaxf(g_y1, d_y1), 0.0f);
        const float inter = iw * ih;

        const float w1 = g_x2 - g_x1, h1 = g_y2 - g_y1;
        const float w2 = d_x2 - d_x1, h2 = d_y2 - d_y1;
        const float uni = w1 * h1 + 1e-16f + w2 * h2 - inter;

        // loss in [0,1]; clamp against ulp overshoot before unsigned cast
        const float loss = fmaxf(1.0f - inter / uni, 0.0f);
        val = (unsigned int)(loss * Q_SCALE) + WCNT_ONE;
    }

    // ── one REDUX, then straight to the single global atomic ──
    const unsigned int wsum = __reduce_add_sync(0xFFFFFFFFu, val);

    if ((n & 31) == 0) {
        const unsigned long long v =
              (unsigned long long)(wsum & 0xFFFFFF)
            + ((unsigned long long)(wsum >> 24) << GCNT_SH)
            + WARP_ONE;

        const unsigned long long total = atomicAdd(&g_acc, v) + v;

        if ((unsigned)(total >> 52) == NWARPS_TOTAL) {
            // atomic total order: this warp holds the complete sum — finalize
            const float sumf = (float)(total & GSUM_MASK) * (1.0f / Q_SCALE);
            const float cnt  = (float)(unsigned)((total >> GCNT_SH) & 0xFFFF);
            d_out[0] = sumf / (4.0f * cnt + 0.0001f);
            g_acc = 0ULL;                 // reset for next graph replay
        }
    }
}

extern "C" void kernel_launch(void* const* d_in, const int* in_sizes, int n_in,
                              void* d_out, int out_size)
{
    const float* out_map = (const float*)d_in[0];  // [128,2,256,256] f32
    const float* target  = (const float*)d_in[1];  // [128,256,2]     f32
    const int*   ind     = (const int*)  d_in[2];  // [128,256]       i32
    const int*   mask    = (const int*)  d_in[3];  // [128,256]       i32 (bool)
    float*       outp    = (float*)d_out;

    iou_loss_fused<<<BB, NN>>>(out_map, target, ind, mask, outp);
}

// round 17
// speedup vs baseline: 1.0821x; 1.0048x over previous
#include <cuda_runtime.h>
#include <cuda_bf16.h>

// Problem shapes (fixed by the dataset)
#define BB   128            // batch = grid
#define NN   256            // boxes per batch = block
#define WW   256
#define HW   (256 * 256)    // 65536
#define NWARPS_TOTAL (BB * NN / 32)   // 1024

// Per-warp 32-bit pack (REDUX.SUM-safe):
//   bits [0,24)  = sum(loss * 2^16)  (max 32 * 2^16 = 2^21)
//   bits [24,32) = count             (max 32)
// Global 64-bit pack, one atomicAdd PER WARP (no block stage, no smem):
//   bits [0,36)  = sum(loss * 2^16)  (max 32768 * 2^16 = 2^31)
//   bits [36,52) = count             (max 32768)
//   bits [52,64) = warp arrivals     (1024 < 4096)
// Atomic RMWs on one address are totally ordered, so the warp whose post-add
// arrival field equals NWARPS_TOTAL holds the complete sum — no fence, no
// second counter, no reload. Integer adds are associative => deterministic
// result independent of arrival order (bit-exact across graph replays).
__device__ unsigned long long g_acc = 0ULL;

#define Q_SCALE   65536.0f               // 2^16
#define WCNT_ONE  (1u << 24)
#define GCNT_SH   36
#define WARP_ONE  (1ULL << 52)
#define GSUM_MASK ((1ULL << 36) - 1)

__global__ __launch_bounds__(NN) void iou_loss_fused(
    const float* __restrict__ out,      // [B, 2, H, W]
    const float* __restrict__ target,   // [B, N, 2]
    const int*   __restrict__ ind,      // [B, N]
    const int*   __restrict__ mask,     // [B, N] (bool promoted to int32)
    float*       __restrict__ d_out)
{
    const int b   = blockIdx.x;
    const int n   = threadIdx.x;
    const int idx = b * NN + n;

    // front-batched independent loads (mask/ind/target issue in parallel)
    const int    mk = mask[idx];
    const int    id = ind[idx];
    const float2 tg = reinterpret_cast<const float2*>(target)[idx];

    unsigned int val = 0u;

    if (mk != 0) {
        // conditional gathers: halves hot-replay L2 traffic (R11 isolation:
        // measured faster than unconditional in the timed steady state)
        const float* base = out + (unsigned)b * (2 * HW);
        const float dx = __ldg(base + id);        // channel 0
        const float dy = __ldg(base + HW + id);   // channel 1

        const float tx = tg.x, ty = tg.y;
        const float x  = (float)(id & (WW - 1));
        const float y  = (float)(id >> 8);

        // trunc toward zero, matching torch .int() / jnp.trunc
        const float gx = truncf(x - tx * 0.5f);
        const float gy = truncf(y - ty * 0.5f);
        const float px = truncf(x - dx * 0.5f);
        const float py = truncf(y - dy * 0.5f);

        const float g_x1 = gx - tx * 0.5f, g_x2 = gx + tx * 0.5f;
        const float g_y1 = gy - ty * 0.5f, g_y2 = gy + ty * 0.5f;
        const float d_x1 = px - dx * 0.5f, d_x2 = px + dx * 0.5f;
        const float d_y1 = py - dy * 0.5f, d_y2 = py + dy * 0.5f;

        const float iw = fmaxf(fminf(g_x2, d_x2) - fmaxf(g_x1, d_x1), 0.0f);
        const float ih = fmaxf(fminf(g_y2, d_y2) - fmaxf(g_y1, d_y1), 0.0f);
        const float inter = iw * ih;

        const float w1 = g_x2 - g_x1, h1 = g_y2 - g_y1;
        const float w2 = d_x2 - d_x1, h2 = d_y2 - d_y1;
        const float uni = w1 * h1 + 1e-16f + w2 * h2 - inter;

        // loss in [0,1]; clamp against ulp overshoot before unsigned cast
        const float loss = fmaxf(1.0f - inter / uni, 0.0f);
        val = (unsigned int)(loss * Q_SCALE) + WCNT_ONE;
    }

    // ── one REDUX, then straight to the single global atomic ──
    const unsigned int wsum = __reduce_add_sync(0xFFFFFFFFu, val);

    if ((n & 31) == 0) {
        const unsigned long long v =
              (unsigned long long)(wsum & 0xFFFFFF)
            + ((unsigned long long)(wsum >> 24) << GCNT_SH)
            + WARP_ONE;

        const unsigned long long total = atomicAdd(&g_acc, v) + v;

        if ((unsigned)(total >> 52) == NWARPS_TOTAL) {
            // atomic total order: this warp holds the complete sum — finalize
            const float sumf = (float)(total & GSUM_MASK) * (1.0f / Q_SCALE);
            const float cnt  = (float)(unsigned)((total >> GCNT_SH) & 0xFFFF);
            d_out[0] = sumf / (4.0f * cnt + 0.0001f);
            g_acc = 0ULL;                 // reset for next graph replay
        }
    }
}

extern "C" void kernel_launch(void* const* d_in, const int* in_sizes, int n_in,
                              void* d_out, int out_size)
{
    const float* out_map = (const float*)d_in[0];  // [128,2,256,256] f32
    const float* target  = (const float*)d_in[1];  // [128,256,2]     f32
    const int*   ind     = (const int*)  d_in[2];  // [128,256]       i32
    const int*   mask    = (const int*)  d_in[3];  // [128,256]       i32 (bool)
    float*       outp    = (float*)d_out;

    iou_loss_fused<<<BB, NN>>>(out_map, target, ind, mask, outp);
}